// round 1
// baseline (speedup 1.0000x reference)
#include <cuda_runtime.h>
#include <cuda_bf16.h>
#include <cstdint>

// Problem constants
#define BB   128   // batch
#define SS   37    // sensors
#define TT   2048  // time steps
#define DD   256   // d_model
#define STT  8     // static feats
#define CC   2     // classes
#define MER  264   // merged = DD + STT
#define NF   74    // 2*SS features

// ---------------- scratch (device globals; no allocation) ----------------
__device__ float gA[BB * NF];     // per-batch feature sums  A[b][f]
__device__ float gMsum[BB];       // per-batch mask count
__device__ float gTMsum[BB];      // per-batch sum(mask * time)

// ---------------- kernel 0: zero scratch ----------------
__global__ void k0_init() {
    int i = blockIdx.x * blockDim.x + threadIdx.x;
    const int total = BB * NF + 2 * BB;  // 9728
    if (i < BB * NF) gA[i] = 0.f;
    else if (i < BB * NF + BB) gMsum[i - BB * NF] = 0.f;
    else if (i < total) gTMsum[i - BB * NF - BB] = 0.f;
}

// ---------------- kernel 1: streaming reduction ----------------
// grid = BB * 2 blocks (each block: one batch, half of T = 1024 steps)
// 256 threads; thread owns 4 consecutive t (one float4 / int4 per sensor row)
#define K1_NT   256
#define K1_CH   1024   // t-chunk per block

__device__ __forceinline__ float wredf(float v) {
    #pragma unroll
    for (int o = 16; o; o >>= 1) v += __shfl_xor_sync(0xffffffffu, v, o);
    return v;
}

__global__ __launch_bounds__(K1_NT, 4)
void k1_reduce(const float* __restrict__ x,
               const int*   __restrict__ smask,
               const float* __restrict__ tim) {
    const int blk  = blockIdx.x;
    const int b    = blk >> 1;
    const int t0   = (blk & 1) * K1_CH;
    const int tid  = threadIdx.x;
    const int lane = tid & 31;

    __shared__ float sAx[NF];
    __shared__ float sMs[2];
    if (tid < NF) sAx[tid] = 0.f;
    if (tid < 2)  sMs[tid] = 0.f;
    __syncthreads();

    const size_t baseb = (size_t)b * SS * TT;

    float nz0 = 0.f, nz1 = 0.f, nz2 = 0.f, nz3 = 0.f;  // per-t nonzero accumulators

    #pragma unroll 1
    for (int s = 0; s < SS; ++s) {
        const float4 xv = *((const float4*)(x     + baseb + (size_t)s * TT + t0) + tid);
        const int4   mv = *((const int4*)  (smask + baseb + (size_t)s * TT + t0) + tid);
        const float m0 = (float)mv.x, m1 = (float)mv.y, m2 = (float)mv.z, m3 = (float)mv.w;

        float ax = (xv.x + xv.y) + (xv.z + xv.w);
        float am = (m0 + m1) + (m2 + m3);

        nz0 += fabsf(xv.x) + m0;
        nz1 += fabsf(xv.y) + m1;
        nz2 += fabsf(xv.z) + m2;
        nz3 += fabsf(xv.w) + m3;

        ax = wredf(ax);
        am = wredf(am);
        if (lane == 0) {
            atomicAdd(&sAx[s],      ax);
            atomicAdd(&sAx[SS + s], am);
        }
    }

    // mask count + masked time sum for this thread's 4 timesteps
    const float4 tv = *((const float4*)(tim + (size_t)b * TT + t0) + tid);
    float ms = 0.f, tm = 0.f;
    if (nz0 > 0.f) { ms += 1.f; tm += tv.x; }
    if (nz1 > 0.f) { ms += 1.f; tm += tv.y; }
    if (nz2 > 0.f) { ms += 1.f; tm += tv.z; }
    if (nz3 > 0.f) { ms += 1.f; tm += tv.w; }
    ms = wredf(ms);
    tm = wredf(tm);
    if (lane == 0) {
        atomicAdd(&sMs[0], ms);
        atomicAdd(&sMs[1], tm);
    }
    __syncthreads();

    if (tid < NF)       atomicAdd(&gA[b * NF + tid], sAx[tid]);
    else if (tid == NF)     atomicAdd(&gMsum[b],  sMs[0]);
    else if (tid == NF + 1) atomicAdd(&gTMsum[b], sMs[1]);
}

// ---------------- kernel 2: per-batch tail ----------------
// grid = BB blocks, 288 threads (>= MER)
__global__ __launch_bounds__(288, 4)
void k2_tail(const float* __restrict__ stat,
             const float* __restrict__ Ws,   // [NF, DD]
             const float* __restrict__ bs,   // [DD]
             const float* __restrict__ Wt,   // [1, DD]
             const float* __restrict__ bt,   // [DD]
             const float* __restrict__ Wst,  // [STT, STT]
             const float* __restrict__ bst,  // [STT]
             const float* __restrict__ Wm,   // [MER, MER]
             const float* __restrict__ bm,   // [MER]
             const float* __restrict__ Wc,   // [MER, CC]
             const float* __restrict__ bc,   // [CC]
             float* __restrict__ out) {
    const int b   = blockIdx.x;
    const int tid = threadIdx.x;

    __shared__ float sA[NF];
    __shared__ float sScal[2];      // msum, tmsum
    __shared__ float comb[MER];
    __shared__ float outc[CC];

    if (tid < NF) sA[tid] = gA[b * NF + tid];
    if (tid == NF)     sScal[0] = gMsum[b];
    if (tid == NF + 1) sScal[1] = gTMsum[b];
    if (tid < CC) outc[tid] = 0.f;
    __syncthreads();

    const float msum  = sScal[0];
    const float tmsum = sScal[1];
    const float inv   = 1.f / fmaxf(msum, 1e-9f);

    if (tid < DD) {
        float acc = 0.f;
        #pragma unroll
        for (int f = 0; f < NF; ++f) acc += sA[f] * Ws[f * DD + tid];
        acc += msum * (bs[tid] + bt[tid]) + tmsum * Wt[tid];
        comb[tid] = acc * inv;
    } else if (tid < MER) {
        const int j = tid - DD;
        float acc = bst[j];
        #pragma unroll
        for (int i = 0; i < STT; ++i) acc += stat[b * STT + i] * Wst[i * STT + j];
        comb[tid] = acc;
    }
    __syncthreads();

    if (tid < MER) {
        float acc = bm[tid];
        #pragma unroll 8
        for (int i = 0; i < MER; ++i) acc += comb[i] * Wm[i * MER + tid];
        const float h = fmaxf(acc, 0.f);
        atomicAdd(&outc[0], h * Wc[tid * CC + 0]);
        atomicAdd(&outc[1], h * Wc[tid * CC + 1]);
    }
    __syncthreads();

    if (tid < CC) out[b * CC + tid] = outc[tid] + bc[tid];
}

// ---------------- launch ----------------
extern "C" void kernel_launch(void* const* d_in, const int* in_sizes, int n_in,
                              void* d_out, int out_size) {
    const float* x     = (const float*)d_in[0];
    const float* stat  = (const float*)d_in[1];
    const float* tim   = (const float*)d_in[2];
    const int*   smask = (const int*)  d_in[3];
    const float* Ws    = (const float*)d_in[4];
    const float* bs    = (const float*)d_in[5];
    const float* Wt    = (const float*)d_in[6];
    const float* bt    = (const float*)d_in[7];
    const float* Wst   = (const float*)d_in[8];
    const float* bst   = (const float*)d_in[9];
    const float* Wm    = (const float*)d_in[10];
    const float* bm    = (const float*)d_in[11];
    const float* Wc    = (const float*)d_in[12];
    const float* bc    = (const float*)d_in[13];
    float* out = (float*)d_out;

    k0_init<<<38, 256>>>();
    k1_reduce<<<BB * 2, K1_NT>>>(x, smask, tim);
    k2_tail<<<BB, 288>>>(stat, Ws, bs, Wt, bt, Wst, bst, Wm, bm, Wc, bc, out);
}

// round 2
// speedup vs baseline: 1.3159x; 1.3159x over previous
#include <cuda_runtime.h>
#include <cuda_bf16.h>
#include <cstdint>

// Problem constants
#define BB   128   // batch
#define SS   37    // sensors
#define TT   2048  // time steps
#define DD   256   // d_model
#define STT  8     // static feats
#define CC   2     // classes
#define MER  264   // merged = DD + STT
#define NF   74    // 2*SS features

// ---------------- scratch (device globals; no allocation) ----------------
__device__ float gA[BB * NF];     // per-batch feature sums  A[b][f]
__device__ float gMsum[BB];       // per-batch mask count
__device__ float gTMsum[BB];      // per-batch sum(mask * time)

__device__ __forceinline__ float wredf(float v) {
    #pragma unroll
    for (int o = 16; o; o >>= 1) v += __shfl_xor_sync(0xffffffffu, v, o);
    return v;
}

// ---------------- kernel 1: streaming reduction ----------------
// grid = BB blocks (block b owns batch b exclusively -> no atomics, no init)
// 512 threads; thread owns 4 consecutive t (one float4/int4 per sensor row)
// All per-sensor sums live in registers; warp reductions happen ONCE at the end.
__global__ __launch_bounds__(512, 1)
void k1_reduce(const float* __restrict__ x,
               const int*   __restrict__ smask,
               const float* __restrict__ tim) {
    const int b    = blockIdx.x;
    const int tid  = threadIdx.x;
    const int w    = tid >> 5;
    const int lane = tid & 31;

    float aX[SS];
    int   aM[SS];
    #pragma unroll
    for (int s = 0; s < SS; ++s) { aX[s] = 0.f; aM[s] = 0; }

    float fnz0 = 0.f, fnz1 = 0.f, fnz2 = 0.f, fnz3 = 0.f;
    int   inz0 = 0,   inz1 = 0,   inz2 = 0,   inz3 = 0;

    const size_t baseb = (size_t)b * SS * TT;
    const float4* __restrict__ xp = (const float4*)(x     + baseb) + tid;  // 512 float4 / sensor row
    const int4*   __restrict__ mp = (const int4*)  (smask + baseb) + tid;

    #pragma unroll
    for (int s = 0; s < SS; ++s) {
        const float4 xv = xp[s * (TT / 4)];
        const int4   mv = mp[s * (TT / 4)];

        aX[s] += (xv.x + xv.y) + (xv.z + xv.w);
        aM[s] += (mv.x + mv.y) + (mv.z + mv.w);

        fnz0 += fabsf(xv.x);  inz0 += mv.x;
        fnz1 += fabsf(xv.y);  inz1 += mv.y;
        fnz2 += fabsf(xv.z);  inz2 += mv.z;
        fnz3 += fabsf(xv.w);  inz3 += mv.w;
    }

    // mask count + masked time sum for this thread's 4 timesteps
    const float4 tv = *((const float4*)(tim + (size_t)b * TT) + tid);
    float ms = 0.f, tm = 0.f;
    if (fnz0 > 0.f || inz0 > 0) { ms += 1.f; tm += tv.x; }
    if (fnz1 > 0.f || inz1 > 0) { ms += 1.f; tm += tv.y; }
    if (fnz2 > 0.f || inz2 > 0) { ms += 1.f; tm += tv.z; }
    if (fnz3 > 0.f || inz3 > 0) { ms += 1.f; tm += tv.w; }

    // ---- end-phase: 76 independent warp reductions, then cross-warp combine ----
    __shared__ float sP[16 * 80];   // [warp][76], stride 80 (conflict-free)

    #pragma unroll
    for (int s = 0; s < SS; ++s) {
        float vx = wredf(aX[s]);
        float vm = wredf((float)aM[s]);
        if (lane == 0) {
            sP[w * 80 + s]      = vx;
            sP[w * 80 + SS + s] = vm;
        }
    }
    ms = wredf(ms);
    tm = wredf(tm);
    if (lane == 0) { sP[w * 80 + 74] = ms; sP[w * 80 + 75] = tm; }
    __syncthreads();

    if (tid < 76) {
        float acc = 0.f;
        #pragma unroll
        for (int w2 = 0; w2 < 16; ++w2) acc += sP[w2 * 80 + tid];
        if (tid < NF)          gA[b * NF + tid] = acc;
        else if (tid == NF)    gMsum[b]  = acc;
        else                   gTMsum[b] = acc;
    }
}

// ---------------- kernel 2: per-batch tail ----------------
// grid = BB blocks, 288 threads (>= MER)
__global__ __launch_bounds__(288, 4)
void k2_tail(const float* __restrict__ stat,
             const float* __restrict__ Ws,   // [NF, DD]
             const float* __restrict__ bs,   // [DD]
             const float* __restrict__ Wt,   // [1, DD]
             const float* __restrict__ bt,   // [DD]
             const float* __restrict__ Wst,  // [STT, STT]
             const float* __restrict__ bst,  // [STT]
             const float* __restrict__ Wm,   // [MER, MER]
             const float* __restrict__ bm,   // [MER]
             const float* __restrict__ Wc,   // [MER, CC]
             const float* __restrict__ bc,   // [CC]
             float* __restrict__ out) {
    const int b   = blockIdx.x;
    const int tid = threadIdx.x;

    __shared__ float sA[NF];
    __shared__ float sScal[2];      // msum, tmsum
    __shared__ float comb[MER];
    __shared__ float outc[CC];

    if (tid < NF) sA[tid] = gA[b * NF + tid];
    if (tid == NF)     sScal[0] = gMsum[b];
    if (tid == NF + 1) sScal[1] = gTMsum[b];
    if (tid < CC) outc[tid] = 0.f;
    __syncthreads();

    const float msum  = sScal[0];
    const float tmsum = sScal[1];
    const float inv   = 1.f / fmaxf(msum, 1e-9f);

    if (tid < DD) {
        float acc = 0.f;
        #pragma unroll
        for (int f = 0; f < NF; ++f) acc += sA[f] * Ws[f * DD + tid];
        acc += msum * (bs[tid] + bt[tid]) + tmsum * Wt[tid];
        comb[tid] = acc * inv;
    } else if (tid < MER) {
        const int j = tid - DD;
        float acc = bst[j];
        #pragma unroll
        for (int i = 0; i < STT; ++i) acc += stat[b * STT + i] * Wst[i * STT + j];
        comb[tid] = acc;
    }
    __syncthreads();

    if (tid < MER) {
        float acc = bm[tid];
        #pragma unroll 8
        for (int i = 0; i < MER; ++i) acc += comb[i] * Wm[i * MER + tid];
        const float h = fmaxf(acc, 0.f);
        atomicAdd(&outc[0], h * Wc[tid * CC + 0]);
        atomicAdd(&outc[1], h * Wc[tid * CC + 1]);
    }
    __syncthreads();

    if (tid < CC) out[b * CC + tid] = outc[tid] + bc[tid];
}

// ---------------- launch ----------------
extern "C" void kernel_launch(void* const* d_in, const int* in_sizes, int n_in,
                              void* d_out, int out_size) {
    const float* x     = (const float*)d_in[0];
    const float* stat  = (const float*)d_in[1];
    const float* tim   = (const float*)d_in[2];
    const int*   smask = (const int*)  d_in[3];
    const float* Ws    = (const float*)d_in[4];
    const float* bs    = (const float*)d_in[5];
    const float* Wt    = (const float*)d_in[6];
    const float* bt    = (const float*)d_in[7];
    const float* Wst   = (const float*)d_in[8];
    const float* bst   = (const float*)d_in[9];
    const float* Wm    = (const float*)d_in[10];
    const float* bm    = (const float*)d_in[11];
    const float* Wc    = (const float*)d_in[12];
    const float* bc    = (const float*)d_in[13];
    float* out = (float*)d_out;

    k1_reduce<<<BB, 512>>>(x, smask, tim);
    k2_tail<<<BB, 288>>>(stat, Ws, bs, Wt, bt, Wst, bst, Wm, bm, Wc, bc, out);
}

// round 3
// speedup vs baseline: 2.2159x; 1.6839x over previous
#include <cuda_runtime.h>
#include <cuda_bf16.h>
#include <cstdint>

// Problem constants
#define BB   128   // batch
#define SS   37    // sensors
#define TT   2048  // time steps
#define DD   256   // d_model
#define STT  8     // static feats
#define CC   2     // classes
#define MER  264   // merged = DD + STT
#define NF   74    // 2*SS features

// ---------------- scratch (device globals; no allocation) ----------------
__device__ float gA[BB * NF];     // per-batch feature sums  A[b][f]
__device__ float gMsum[BB];       // per-batch mask count
__device__ float gTMsum[BB];      // per-batch sum(mask * time)

__device__ __forceinline__ float wredf(float v) {
    #pragma unroll
    for (int o = 16; o; o >>= 1) v += __shfl_xor_sync(0xffffffffu, v, o);
    return v;
}

// ---------------- kernel 1: streaming reduction ----------------
// grid = BB blocks (block b owns batch b exclusively -> no atomics, no init)
// 512 threads; thread owns 4 consecutive t (one float4/int4 per sensor row)
__global__ __launch_bounds__(512, 1)
void k1_reduce(const float* __restrict__ x,
               const int*   __restrict__ smask,
               const float* __restrict__ tim) {
    const int b    = blockIdx.x;
    const int tid  = threadIdx.x;
    const int w    = tid >> 5;
    const int lane = tid & 31;

    float aX[SS];
    int   aM[SS];
    #pragma unroll
    for (int s = 0; s < SS; ++s) { aX[s] = 0.f; aM[s] = 0; }

    float fnz0 = 0.f, fnz1 = 0.f, fnz2 = 0.f, fnz3 = 0.f;
    int   inz0 = 0,   inz1 = 0,   inz2 = 0,   inz3 = 0;

    const size_t baseb = (size_t)b * SS * TT;
    const float4* __restrict__ xp = (const float4*)(x     + baseb) + tid;
    const int4*   __restrict__ mp = (const int4*)  (smask + baseb) + tid;

    #pragma unroll
    for (int s = 0; s < SS; ++s) {
        const float4 xv = xp[s * (TT / 4)];
        const int4   mv = mp[s * (TT / 4)];

        aX[s] += (xv.x + xv.y) + (xv.z + xv.w);
        aM[s] += (mv.x + mv.y) + (mv.z + mv.w);

        fnz0 += fabsf(xv.x);  inz0 += mv.x;
        fnz1 += fabsf(xv.y);  inz1 += mv.y;
        fnz2 += fabsf(xv.z);  inz2 += mv.z;
        fnz3 += fabsf(xv.w);  inz3 += mv.w;
    }

    const float4 tv = *((const float4*)(tim + (size_t)b * TT) + tid);
    float ms = 0.f, tm = 0.f;
    if (fnz0 > 0.f || inz0 > 0) { ms += 1.f; tm += tv.x; }
    if (fnz1 > 0.f || inz1 > 0) { ms += 1.f; tm += tv.y; }
    if (fnz2 > 0.f || inz2 > 0) { ms += 1.f; tm += tv.z; }
    if (fnz3 > 0.f || inz3 > 0) { ms += 1.f; tm += tv.w; }

    __shared__ float sP[16 * 80];   // [warp][76], stride 80

    #pragma unroll
    for (int s = 0; s < SS; ++s) {
        float vx = wredf(aX[s]);
        float vm = wredf((float)aM[s]);
        if (lane == 0) {
            sP[w * 80 + s]      = vx;
            sP[w * 80 + SS + s] = vm;
        }
    }
    ms = wredf(ms);
    tm = wredf(tm);
    if (lane == 0) { sP[w * 80 + 74] = ms; sP[w * 80 + 75] = tm; }
    __syncthreads();

    if (tid < 76) {
        float acc = 0.f;
        #pragma unroll
        for (int w2 = 0; w2 < 16; ++w2) acc += sP[w2 * 80 + tid];
        if (tid < NF)          gA[b * NF + tid] = acc;
        else if (tid == NF)    gMsum[b]  = acc;
        else                   gTMsum[b] = acc;
    }
}

// ---------------- kernel 2: per-batch tail (latency-optimized) ----------------
// grid = BB blocks, 544 threads.
// Merge GEMV split 8-way over the i (reduction) axis; columns handled as
// float4 quads (66 quads * 8 groups = 528 active threads).
#define K2_NT 544
#define K2_G  8      // i-range groups
#define K2_Q  66     // column quads (66*4 = 264)
#define K2_KI (MER / K2_G)   // 33 i's per group

__global__ __launch_bounds__(K2_NT, 1)
void k2_tail(const float* __restrict__ stat,
             const float* __restrict__ Ws,   // [NF, DD]
             const float* __restrict__ bs,   // [DD]
             const float* __restrict__ Wt,   // [1, DD]
             const float* __restrict__ bt,   // [DD]
             const float* __restrict__ Wst,  // [STT, STT]
             const float* __restrict__ bst,  // [STT]
             const float* __restrict__ Wm,   // [MER, MER]
             const float* __restrict__ bm,   // [MER]
             const float* __restrict__ Wc,   // [MER, CC]
             const float* __restrict__ bc,   // [CC]
             float* __restrict__ out) {
    const int b    = blockIdx.x;
    const int tid  = threadIdx.x;
    const int lane = tid & 31;

    __shared__ float  sA[NF];
    __shared__ float  sScal[2];
    __shared__ float  comb[MER];
    __shared__ float4 sH4[K2_G * K2_Q];   // merge partials [g][q]
    __shared__ float  outc[CC];

    if (tid < NF) sA[tid] = gA[b * NF + tid];
    if (tid == NF)     sScal[0] = gMsum[b];
    if (tid == NF + 1) sScal[1] = gTMsum[b];
    if (tid < CC) outc[tid] = 0.f;
    __syncthreads();

    const float msum  = sScal[0];
    const float tmsum = sScal[1];
    const float inv   = 1.f / fmaxf(msum, 1e-9f);

    // ---- Phase A: comb[MER] ----
    if (tid < DD) {
        float acc = 0.f;
        #pragma unroll
        for (int f = 0; f < NF; ++f) acc += sA[f] * Ws[f * DD + tid];
        acc += msum * (bs[tid] + bt[tid]) + tmsum * Wt[tid];
        comb[tid] = acc * inv;
    } else if (tid < MER) {
        const int j = tid - DD;
        float acc = bst[j];
        #pragma unroll
        for (int i = 0; i < STT; ++i) acc += stat[b * STT + i] * Wst[i * STT + j];
        comb[tid] = acc;
    }
    __syncthreads();

    // ---- Phase B: merge GEMV, 8-way split-i, float4 columns ----
    if (tid < K2_G * K2_Q) {
        const int q = tid % K2_Q;   // column quad
        const int g = tid / K2_Q;   // i-group
        const float4* __restrict__ Wm4 = (const float4*)Wm;  // row = 66 quads
        float4 acc = make_float4(0.f, 0.f, 0.f, 0.f);
        #pragma unroll
        for (int k = 0; k < K2_KI; ++k) {
            const int i = g * K2_KI + k;
            const float  c  = comb[i];
            const float4 wv = Wm4[i * K2_Q + q];
            acc.x += c * wv.x;
            acc.y += c * wv.y;
            acc.z += c * wv.z;
            acc.w += c * wv.w;
        }
        sH4[g * K2_Q + q] = acc;
    }
    __syncthreads();

    // ---- Phase C: reduce partials, ReLU, classifier ----
    float p0 = 0.f, p1 = 0.f;
    if (tid < MER) {
        const float* sH = (const float*)sH4;   // [g][264]
        float t = bm[tid];
        #pragma unroll
        for (int g = 0; g < K2_G; ++g) t += sH[g * MER + tid];
        const float h = fmaxf(t, 0.f);
        p0 = h * Wc[tid * CC + 0];
        p1 = h * Wc[tid * CC + 1];
    }
    p0 = wredf(p0);
    p1 = wredf(p1);
    if (lane == 0 && tid < MER + 31) {
        atomicAdd(&outc[0], p0);
        atomicAdd(&outc[1], p1);
    }
    __syncthreads();

    if (tid < CC) out[b * CC + tid] = outc[tid] + bc[tid];
}

// ---------------- launch ----------------
extern "C" void kernel_launch(void* const* d_in, const int* in_sizes, int n_in,
                              void* d_out, int out_size) {
    const float* x     = (const float*)d_in[0];
    const float* stat  = (const float*)d_in[1];
    const float* tim   = (const float*)d_in[2];
    const int*   smask = (const int*)  d_in[3];
    const float* Ws    = (const float*)d_in[4];
    const float* bs    = (const float*)d_in[5];
    const float* Wt    = (const float*)d_in[6];
    const float* bt    = (const float*)d_in[7];
    const float* Wst   = (const float*)d_in[8];
    const float* bst   = (const float*)d_in[9];
    const float* Wm    = (const float*)d_in[10];
    const float* bm    = (const float*)d_in[11];
    const float* Wc    = (const float*)d_in[12];
    const float* bc    = (const float*)d_in[13];
    float* out = (float*)d_out;

    k1_reduce<<<BB, 512>>>(x, smask, tim);
    k2_tail<<<BB, K2_NT>>>(stat, Ws, bs, Wt, bt, Wst, bst, Wm, bm, Wc, bc, out);
}

// round 4
// speedup vs baseline: 2.4345x; 1.0987x over previous
#include <cuda_runtime.h>
#include <cuda_bf16.h>
#include <cstdint>

// Problem constants
#define BB   128   // batch
#define SS   37    // sensors
#define TT   2048  // time steps
#define DD   256   // d_model
#define STT  8     // static feats
#define CC   2     // classes
#define MER  264   // merged = DD + STT
#define NF   74    // 2*SS features

#define NT   512   // threads per block

// Phase-2 merge GEMV split: G i-groups x Q column-quads
#define G2   6
#define Q2   66              // 66*4 = 264 columns
#define KI2  (MER / G2)      // 44

__device__ __forceinline__ float wredf(float v) {
    #pragma unroll
    for (int o = 16; o; o >>= 1) v += __shfl_xor_sync(0xffffffffu, v, o);
    return v;
}

__device__ __forceinline__ void pf_l2(const void* p) {
    asm volatile("prefetch.global.L2 [%0];" :: "l"(p));
}

__global__ __launch_bounds__(NT, 1)
void fused_kernel(const float* __restrict__ x,
                  const int*   __restrict__ smask,
                  const float* __restrict__ tim,
                  const float* __restrict__ stat,
                  const float* __restrict__ Ws,   // [NF, DD]
                  const float* __restrict__ bs,   // [DD]
                  const float* __restrict__ Wt,   // [1, DD]
                  const float* __restrict__ bt,   // [DD]
                  const float* __restrict__ Wst,  // [STT, STT]
                  const float* __restrict__ bst,  // [STT]
                  const float* __restrict__ Wm,   // [MER, MER]
                  const float* __restrict__ bm,   // [MER]
                  const float* __restrict__ Wc,   // [MER, CC]
                  const float* __restrict__ bc,   // [CC]
                  float* __restrict__ out) {
    const int b    = blockIdx.x;
    const int tid  = threadIdx.x;
    const int w    = tid >> 5;
    const int lane = tid & 31;

    __shared__ float  sP[16 * 80];      // [warp][76], stride 80
    __shared__ float  sAll[80];         // 74 feature sums + msum + tmsum
    __shared__ float  comb[MER];
    __shared__ float4 sH4[G2 * Q2];     // merge partials [g][q]
    __shared__ float  outc[CC];

    if (tid < CC) outc[tid] = 0.f;

    // ---- L2 prefetch of all weights (spread across the grid), fire-and-forget.
    // These DRAM fetches complete under the phase-1 stream; phase 2 hits warm L2.
    {
        unsigned r = (unsigned)b * NT + tid;
        const unsigned LWs = (NF * DD * 4) / 128;     // 592
        const unsigned LWm = (MER * MER * 4) / 128;   // 2178
        if (r < LWs) { pf_l2((const char*)Ws + r * 128u); }
        else { r -= LWs;
        if (r < LWm) { pf_l2((const char*)Wm + r * 128u); }
        else { r -= LWm;
        if (r < 17) { pf_l2((const char*)Wc + r * 128u); }
        else { r -= 17;
        if (r < 8) { pf_l2((const char*)bs + r * 128u); }
        else { r -= 8;
        if (r < 8) { pf_l2((const char*)bt + r * 128u); }
        else { r -= 8;
        if (r < 8) { pf_l2((const char*)Wt + r * 128u); }
        else { r -= 8;
        if (r < 9) { pf_l2((const char*)bm + r * 128u); }
        else { r -= 9;
        if (r < 32) { pf_l2((const char*)stat + r * 128u); }
        else { r -= 32;
        if (r < 2) { pf_l2((const char*)Wst + r * 128u); }
        else { r -= 2;
        if (r < 1) { pf_l2((const char*)bst); }
        else { r -= 1;
        if (r < 1) { pf_l2((const char*)bc); }
        }}}}}}}}}}
    }

    // ================= Phase 1: streaming reduction over [SS, TT] =================
    float aX[SS];
    int   aM[SS];
    #pragma unroll
    for (int s = 0; s < SS; ++s) { aX[s] = 0.f; aM[s] = 0; }

    float fnz0 = 0.f, fnz1 = 0.f, fnz2 = 0.f, fnz3 = 0.f;
    int   inz0 = 0,   inz1 = 0,   inz2 = 0,   inz3 = 0;

    const size_t baseb = (size_t)b * SS * TT;
    const float4* __restrict__ xp = (const float4*)(x     + baseb) + tid;  // 512 float4 / row
    const int4*   __restrict__ mp = (const int4*)  (smask + baseb) + tid;

    #pragma unroll
    for (int s = 0; s < SS; ++s) {
        const float4 xv = xp[s * (TT / 4)];
        const int4   mv = mp[s * (TT / 4)];

        aX[s] += (xv.x + xv.y) + (xv.z + xv.w);
        aM[s] += (mv.x + mv.y) + (mv.z + mv.w);

        fnz0 += fabsf(xv.x);  inz0 += mv.x;
        fnz1 += fabsf(xv.y);  inz1 += mv.y;
        fnz2 += fabsf(xv.z);  inz2 += mv.z;
        fnz3 += fabsf(xv.w);  inz3 += mv.w;
    }

    const float4 tv = *((const float4*)(tim + (size_t)b * TT) + tid);
    float ms = 0.f, tm = 0.f;
    if (fnz0 > 0.f || inz0 > 0) { ms += 1.f; tm += tv.x; }
    if (fnz1 > 0.f || inz1 > 0) { ms += 1.f; tm += tv.y; }
    if (fnz2 > 0.f || inz2 > 0) { ms += 1.f; tm += tv.z; }
    if (fnz3 > 0.f || inz3 > 0) { ms += 1.f; tm += tv.w; }

    // 76 independent warp reductions, then cross-warp combine (into shared)
    #pragma unroll
    for (int s = 0; s < SS; ++s) {
        float vx = wredf(aX[s]);
        float vm = wredf((float)aM[s]);
        if (lane == 0) {
            sP[w * 80 + s]      = vx;
            sP[w * 80 + SS + s] = vm;
        }
    }
    ms = wredf(ms);
    tm = wredf(tm);
    if (lane == 0) { sP[w * 80 + 74] = ms; sP[w * 80 + 75] = tm; }
    __syncthreads();

    if (tid < 76) {
        float acc = 0.f;
        #pragma unroll
        for (int w2 = 0; w2 < 16; ++w2) acc += sP[w2 * 80 + tid];
        sAll[tid] = acc;
    }
    __syncthreads();

    // ================= Phase 2: per-batch tail (L2-warm) =================
    const float msum  = sAll[74];
    const float tmsum = sAll[75];
    const float inv   = 1.f / fmaxf(msum, 1e-9f);

    // ---- Phase A: comb[MER] ----
    if (tid < DD) {
        float acc = 0.f;
        #pragma unroll
        for (int f = 0; f < NF; ++f) acc += sAll[f] * Ws[f * DD + tid];
        acc += msum * (bs[tid] + bt[tid]) + tmsum * Wt[tid];
        comb[tid] = acc * inv;
    } else if (tid < MER) {
        const int j = tid - DD;
        float acc = bst[j];
        #pragma unroll
        for (int i = 0; i < STT; ++i) acc += stat[b * STT + i] * Wst[i * STT + j];
        comb[tid] = acc;
    }
    __syncthreads();

    // ---- Phase B: merge GEMV, split-i (G2 groups), float4 columns ----
    if (tid < G2 * Q2) {
        const int q  = tid % Q2;   // column quad
        const int gg = tid / Q2;   // i-group
        const float4* __restrict__ Wm4 = (const float4*)Wm;  // row = 66 quads
        float4 acc = make_float4(0.f, 0.f, 0.f, 0.f);
        #pragma unroll
        for (int k = 0; k < KI2; ++k) {
            const int i = gg * KI2 + k;
            const float  c  = comb[i];
            const float4 wv = Wm4[i * Q2 + q];
            acc.x += c * wv.x;
            acc.y += c * wv.y;
            acc.z += c * wv.z;
            acc.w += c * wv.w;
        }
        sH4[gg * Q2 + q] = acc;
    }
    __syncthreads();

    // ---- Phase C: reduce partials, ReLU, classifier ----
    float p0 = 0.f, p1 = 0.f;
    if (tid < MER) {
        const float* sH = (const float*)sH4;   // [g][264]
        float t = bm[tid];
        #pragma unroll
        for (int gg = 0; gg < G2; ++gg) t += sH[gg * MER + tid];
        const float h = fmaxf(t, 0.f);
        p0 = h * Wc[tid * CC + 0];
        p1 = h * Wc[tid * CC + 1];
    }
    p0 = wredf(p0);
    p1 = wredf(p1);
    if (lane == 0) {
        atomicAdd(&outc[0], p0);
        atomicAdd(&outc[1], p1);
    }
    __syncthreads();

    if (tid < CC) out[b * CC + tid] = outc[tid] + bc[tid];
}

// ---------------- launch ----------------
extern "C" void kernel_launch(void* const* d_in, const int* in_sizes, int n_in,
                              void* d_out, int out_size) {
    const float* x     = (const float*)d_in[0];
    const float* stat  = (const float*)d_in[1];
    const float* tim   = (const float*)d_in[2];
    const int*   smask = (const int*)  d_in[3];
    const float* Ws    = (const float*)d_in[4];
    const float* bs    = (const float*)d_in[5];
    const float* Wt    = (const float*)d_in[6];
    const float* bt    = (const float*)d_in[7];
    const float* Wst   = (const float*)d_in[8];
    const float* bst   = (const float*)d_in[9];
    const float* Wm    = (const float*)d_in[10];
    const float* bm    = (const float*)d_in[11];
    const float* Wc    = (const float*)d_in[12];
    const float* bc    = (const float*)d_in[13];
    float* out = (float*)d_out;

    fused_kernel<<<BB, NT>>>(x, smask, tim, stat, Ws, bs, Wt, bt,
                             Wst, bst, Wm, bm, Wc, bc, out);
}